// round 11
// baseline (speedup 1.0000x reference)
#include <cuda_runtime.h>
#include <math.h>

#define KP 4096
#define BP 8
#define THREADS 256          // 8 warps = 8 j-segments
#define WARPS 8
#define TILE_I 64            // i-points per block
#define IPT 2                // i-points per thread (lane l owns i = ibase + l + 32k)
#define TILE_J 1024          // j-points per smem tile
#define NTILE (KP / TILE_J)  // 4
#define WPAIRS (TILE_J / 2 / WARPS)  // 64 packed pairs per warp per tile
#define SMEM_FLOATS (8 * TILE_J)     // O-tile (4 arrays) + A-tile (4 arrays)
#define SMEM_BYTES (SMEM_FLOATS * 4) // 32 KB

#define W_CHAMFER 5.0f
#define W_KNN 3.0f
#define ALPHA 1.05f

__device__ float g_cham[BP * KP];
__device__ float g_value[BP * KP];
__device__ float g_batch[BP];

typedef unsigned long long u64;

__device__ __forceinline__ u64 pk2(float lo, float hi) {
    u64 r;
    asm("mov.b64 %0, {%1, %2};" : "=l"(r) : "f"(lo), "f"(hi));
    return r;
}
__device__ __forceinline__ void upk2(u64 v, float& lo, float& hi) {
    asm("mov.b64 {%0, %1}, %2;" : "=f"(lo), "=f"(hi) : "l"(v));
}
__device__ __forceinline__ u64 ffma2(u64 a, u64 b, u64 c) {
    u64 d;
    asm("fma.rn.f32x2 %0, %1, %2, %3;" : "=l"(d) : "l"(a), "l"(b), "l"(c));
    return d;
}

// Unconditional insert of d into ascending sorted 6-array (keeps 6 smallest).
// Safe no-op when d >= h[5].
__device__ __forceinline__ void insert6(float (&h)[6], float d) {
    h[5] = fminf(h[5], d);
#pragma unroll
    for (int m = 5; m >= 1; --m) {
        float lo = fminf(h[m - 1], h[m]);
        float hi = fmaxf(h[m - 1], h[m]);
        h[m - 1] = lo;
        h[m] = hi;
    }
}
// Guarded insert (merge paths / rare second value).
__device__ __forceinline__ void heap_insert(float (&h)[6], float d) {
    if (d < h[5]) insert6(h, d);
}

__global__ void __launch_bounds__(THREADS, 4)
dist_kernel(const float* __restrict__ adv, const float* __restrict__ ori) {
    extern __shared__ float sm[];
    // O-tile SoA
    float* s_ox = sm;
    float* s_oy = sm + TILE_J;
    float* s_oz = sm + 2 * TILE_J;
    float* s_os = sm + 3 * TILE_J;
    // A-tile SoA
    float* s_ax = sm + 4 * TILE_J;
    float* s_ay = sm + 5 * TILE_J;
    float* s_az = sm + 6 * TILE_J;
    float* s_as = sm + 7 * TILE_J;
    const u64* s_ox2 = (const u64*)s_ox;
    const u64* s_oy2 = (const u64*)s_oy;
    const u64* s_oz2 = (const u64*)s_oz;
    const u64* s_os2 = (const u64*)s_os;
    const u64* s_ax2 = (const u64*)s_ax;
    const u64* s_ay2 = (const u64*)s_ay;
    const u64* s_az2 = (const u64*)s_az;
    const u64* s_as2 = (const u64*)s_as;

    const int b   = blockIdx.y;
    const int tid = threadIdx.x;
    const int seg = tid >> 5;        // warp id = j-segment (0..7)
    const int l   = tid & 31;        // lane
    const int ibase = blockIdx.x * TILE_I;
    const float* A = adv + (size_t)b * KP * 3;
    const float* O = ori + (size_t)b * KP * 3;
    const unsigned full = 0xffffffffu;

    // Per-thread i-points: i = ibase + l + 32*k
    u64 mx2[IPT], my2[IPT], mz2[IPT];
    float ci[IPT], cl[IPT], ch[IPT];
    float h[IPT][6];
#pragma unroll
    for (int k = 0; k < IPT; ++k) {
        int i = ibase + l + 32 * k;
        float x = A[3 * i + 0], y = A[3 * i + 1], z = A[3 * i + 2];
        float mx = -2.0f * x, my = -2.0f * y, mz = -2.0f * z;
        mx2[k] = pk2(mx, mx);
        my2[k] = pk2(my, my);
        mz2[k] = pk2(mz, mz);
        ci[k] = fmaf(x, x, fmaf(y, y, z * z));
        cl[k] = 3.4e38f; ch[k] = 3.4e38f;
#pragma unroll
        for (int m = 0; m < 6; ++m) h[k][m] = 3.4e38f;
    }

    // ---- Fused pass: chamfer (vs ori) + kNN (vs adv) per tile ----
    // Distances EXCLUDE +ci (re-added at the end; order-invariant offset).
    for (int t = 0; t < NTILE; ++t) {
        __syncthreads();
        const float* PO = O + (size_t)(t * TILE_J) * 3;
        const float* PA = A + (size_t)(t * TILE_J) * 3;
        for (int j = tid; j < TILE_J; j += THREADS) {
            float x = PO[3 * j + 0], y = PO[3 * j + 1], z = PO[3 * j + 2];
            s_ox[j] = x; s_oy[j] = y; s_oz[j] = z;
            s_os[j] = fmaf(x, x, fmaf(y, y, z * z));
            x = PA[3 * j + 0]; y = PA[3 * j + 1]; z = PA[3 * j + 2];
            s_ax[j] = x; s_ay[j] = y; s_az[j] = z;
            s_as[j] = fmaf(x, x, fmaf(y, y, z * z));
        }
        __syncthreads();

        const int pbeg = seg * WPAIRS;
#pragma unroll 4
        for (int p = pbeg; p < pbeg + WPAIRS; ++p) {
            // chamfer chain (independent of knn chain -> ILP)
            u64 oxj = s_ox2[p], oyj = s_oy2[p], ozj = s_oz2[p], osj = s_os2[p];
            // knn chain
            u64 axj = s_ax2[p], ayj = s_ay2[p], azj = s_az2[p], asj = s_as2[p];
#pragma unroll
            for (int k = 0; k < IPT; ++k) {
                u64 dc = ffma2(mz2[k], ozj, ffma2(my2[k], oyj, ffma2(mx2[k], oxj, osj)));
                u64 dk = ffma2(mz2[k], azj, ffma2(my2[k], ayj, ffma2(mx2[k], axj, asj)));
                float cdl, cdh, kdl, kdh;
                upk2(dc, cdl, cdh);
                cl[k] = fminf(cl[k], cdl);
                ch[k] = fminf(ch[k], cdh);
                upk2(dk, kdl, kdh);
                float mn = fminf(kdl, kdh);
                float mx = fmaxf(kdl, kdh);
                // Branchless hot path (no-op when mn doesn't qualify)
                insert6(h[k], mn);
                // Both-of-pair qualify is rare -> mostly-skipped warp branch
                bool c = mx < h[k][5];
                if (__any_sync(full, c)) {
                    if (c) insert6(h[k], mx);
                }
            }
        }
    }

    // Fold packed chamfer halves
    float cmin[IPT];
#pragma unroll
    for (int k = 0; k < IPT; ++k) cmin[k] = fminf(cl[k], ch[k]);

    // ---- Cross-warp merge (3-round tree), reusing tile smem as buffer ----
    float* buf = sm;

#define MERGE_WRITE(SLOT)                                                   \
    {                                                                       \
        float* w = buf + (((size_t)(SLOT) * 32 + l) * IPT) * 7;             \
        _Pragma("unroll")                                                   \
        for (int k = 0; k < IPT; ++k) {                                     \
            w[k * 7 + 0] = cmin[k];                                         \
            _Pragma("unroll")                                               \
            for (int m = 0; m < 6; ++m) w[k * 7 + 1 + m] = h[k][m];         \
        }                                                                   \
    }
#define MERGE_READ(SLOT)                                                    \
    {                                                                       \
        const float* r = buf + (((size_t)(SLOT) * 32 + l) * IPT) * 7;       \
        _Pragma("unroll")                                                   \
        for (int k = 0; k < IPT; ++k) {                                     \
            cmin[k] = fminf(cmin[k], r[k * 7 + 0]);                         \
            _Pragma("unroll")                                               \
            for (int m = 0; m < 6; ++m) heap_insert(h[k], r[k * 7 + 1 + m]);\
        }                                                                   \
    }

    __syncthreads();
    if (seg >= 4) MERGE_WRITE(seg - 4);
    __syncthreads();
    if (seg < 4) MERGE_READ(seg);
    __syncthreads();
    if (seg == 2 || seg == 3) MERGE_WRITE(seg - 2);
    __syncthreads();
    if (seg < 2) MERGE_READ(seg);
    __syncthreads();
    if (seg == 1) MERGE_WRITE(0);
    __syncthreads();
    if (seg == 0) {
        MERGE_READ(0);
#pragma unroll
        for (int k = 0; k < IPT; ++k) {
            int i = ibase + l + 32 * k;
            g_cham[b * KP + i] = cmin[k] + ci[k];
            // drop h[0] (self), mean of next 5, re-add ci offset
            g_value[b * KP + i] =
                fmaf(0.2f, h[k][1] + h[k][2] + h[k][3] + h[k][4] + h[k][5], ci[k]);
        }
    }
}

// Warp-shuffle block reduction (256 thr): result valid in thread 0.
__device__ __forceinline__ float block_sum(float v, float* red) {
    const unsigned full = 0xffffffffu;
#pragma unroll
    for (int o = 16; o > 0; o >>= 1) v += __shfl_xor_sync(full, v, o);
    const int w = threadIdx.x >> 5;
    if ((threadIdx.x & 31) == 0) red[w] = v;
    __syncthreads();
    float r = 0.0f;
    if (threadIdx.x < 8) r = red[threadIdx.x];
#pragma unroll
    for (int o = 4; o > 0; o >>= 1) r += __shfl_xor_sync(full, r, o);
    __syncthreads();
    return r;   // thread 0 holds the sum
}

__global__ void __launch_bounds__(256)
reduce_kernel() {
    __shared__ float red[8];
    __shared__ float s_bcast[2];
    const int b = blockIdx.x;
    const int tid = threadIdx.x;
    const float* cham = g_cham + b * KP;
    const float* val  = g_value + b * KP;

    float s1 = 0.0f, s2 = 0.0f;
    for (int i = tid; i < KP; i += 256) { s1 += cham[i]; s2 += val[i]; }
    float cham_sum = block_sum(s1, red);
    float val_sum  = block_sum(s2, red);
    if (tid == 0) s_bcast[0] = val_sum * (1.0f / KP);
    __syncthreads();
    float mean = s_bcast[0];

    float s3 = 0.0f;
    for (int i = tid; i < KP; i += 256) {
        float d = val[i] - mean;
        s3 = fmaf(d, d, s3);
    }
    float var_sum = block_sum(s3, red);
    if (tid == 0) {
        float stdv = sqrtf(var_sum * (1.0f / (KP - 1)));   // ddof=1
        s_bcast[1] = fmaf(ALPHA, stdv, mean);
    }
    __syncthreads();
    float thr = s_bcast[1];

    float s4 = 0.0f;
    for (int i = tid; i < KP; i += 256) {
        float v = val[i];
        if (v > thr) s4 += v;
    }
    float msum = block_sum(s4, red);

    if (tid == 0) {
        float cham_mean = cham_sum * (1.0f / KP);
        float knn_mean  = msum * (1.0f / KP);
        g_batch[b] = cham_mean * W_CHAMFER + knn_mean * W_KNN;
    }
}

__global__ void final_kernel(float* __restrict__ out) {
    if (threadIdx.x == 0) {
        float s = 0.0f;
#pragma unroll
        for (int b = 0; b < BP; ++b) s += g_batch[b];
        out[0] = s * (1.0f / BP);
    }
}

extern "C" void kernel_launch(void* const* d_in, const int* in_sizes, int n_in,
                              void* d_out, int out_size) {
    const float* adv = (const float*)d_in[0];
    const float* ori = (const float*)d_in[1];
    float* out = (float*)d_out;

    dist_kernel<<<dim3(KP / TILE_I, BP), THREADS, SMEM_BYTES>>>(adv, ori);
    reduce_kernel<<<BP, 256>>>();
    final_kernel<<<1, 32>>>(out);
}

// round 12
// speedup vs baseline: 1.1461x; 1.1461x over previous
#include <cuda_runtime.h>
#include <math.h>

#define KP 4096
#define BP 8
#define THREADS 256          // 8 warps = 8 j-segments
#define WARPS 8
#define TILE_I 64            // i-points per block
#define IPT 2                // i-points per thread (lane l owns i = ibase + l + 32k)
#define TILE_J 1024          // j-points per smem tile
#define NTILE (KP / TILE_J)  // 4
#define WPAIRS (TILE_J / 2 / WARPS)  // 64 packed pairs per warp per tile
#define SMEM_FLOATS (4 * TILE_J)
#define SMEM_BYTES (SMEM_FLOATS * 4)   // 16 KB

#define W_CHAMFER 5.0f
#define W_KNN 3.0f
#define ALPHA 1.05f

__device__ float g_cham[BP * KP];
__device__ float g_value[BP * KP];
__device__ float g_batch[BP];

typedef unsigned long long u64;

__device__ __forceinline__ u64 pk2(float lo, float hi) {
    u64 r;
    asm("mov.b64 %0, {%1, %2};" : "=l"(r) : "f"(lo), "f"(hi));
    return r;
}
__device__ __forceinline__ void upk2(u64 v, float& lo, float& hi) {
    asm("mov.b64 {%0, %1}, %2;" : "=f"(lo), "=f"(hi) : "l"(v));
}
__device__ __forceinline__ u64 ffma2(u64 a, u64 b, u64 c) {
    u64 d;
    asm("fma.rn.f32x2 %0, %1, %2, %3;" : "=l"(d) : "l"(a), "l"(b), "l"(c));
    return d;
}

// Unconditional insert of d into ascending sorted 6-array (keeps 6 smallest).
// Safe no-op when d >= h[5].
__device__ __forceinline__ void insert6(float (&h)[6], float d) {
    h[5] = fminf(h[5], d);
#pragma unroll
    for (int m = 5; m >= 1; --m) {
        float lo = fminf(h[m - 1], h[m]);
        float hi = fmaxf(h[m - 1], h[m]);
        h[m - 1] = lo;
        h[m] = hi;
    }
}
// Guarded insert (merge paths).
__device__ __forceinline__ void heap_insert(float (&h)[6], float d) {
    if (d < h[5]) insert6(h, d);
}

__global__ void __launch_bounds__(THREADS)
dist_kernel(const float* __restrict__ adv, const float* __restrict__ ori) {
    extern __shared__ float sm[];
    float* s_x = sm;
    float* s_y = sm + TILE_J;
    float* s_z = sm + 2 * TILE_J;
    float* s_s = sm + 3 * TILE_J;
    const u64* s_x2 = (const u64*)s_x;   // direct LDS.64 into packed pairs
    const u64* s_y2 = (const u64*)s_y;
    const u64* s_z2 = (const u64*)s_z;
    const u64* s_s2 = (const u64*)s_s;

    const int b   = blockIdx.y;
    const int tid = threadIdx.x;
    const int seg = tid >> 5;        // warp id = j-segment (0..7)
    const int l   = tid & 31;        // lane
    const int ibase = blockIdx.x * TILE_I;
    const float* A = adv + (size_t)b * KP * 3;
    const float* O = ori + (size_t)b * KP * 3;
    const unsigned full = 0xffffffffu;

    // Per-thread i-points: i = ibase + l + 32*k
    u64 mx2[IPT], my2[IPT], mz2[IPT];
    float ci[IPT], cl[IPT], ch[IPT];
    float h[IPT][6];
#pragma unroll
    for (int k = 0; k < IPT; ++k) {
        int i = ibase + l + 32 * k;
        float x = A[3 * i + 0], y = A[3 * i + 1], z = A[3 * i + 2];
        float mx = -2.0f * x, my = -2.0f * y, mz = -2.0f * z;
        mx2[k] = pk2(mx, mx);
        my2[k] = pk2(my, my);
        mz2[k] = pk2(mz, mz);
        ci[k] = fmaf(x, x, fmaf(y, y, z * z));
        cl[k] = 3.4e38f; ch[k] = 3.4e38f;
#pragma unroll
        for (int m = 0; m < 6; ++m) h[k][m] = 3.4e38f;
    }

    // ---- Phase 1: Chamfer (min over ori). Distances EXCLUDE +ci (added at end). ----
    for (int t = 0; t < NTILE; ++t) {
        __syncthreads();
        const float* P = O + (size_t)(t * TILE_J) * 3;
        for (int j = tid; j < TILE_J; j += THREADS) {
            float x = P[3 * j + 0], y = P[3 * j + 1], z = P[3 * j + 2];
            s_x[j] = x; s_y[j] = y; s_z[j] = z;
            s_s[j] = fmaf(x, x, fmaf(y, y, z * z));
        }
        __syncthreads();

        const int pbeg = seg * WPAIRS;
#pragma unroll 8
        for (int p = pbeg; p < pbeg + WPAIRS; ++p) {
            u64 xj = s_x2[p], yj = s_y2[p], zj = s_z2[p], sj = s_s2[p];
#pragma unroll
            for (int k = 0; k < IPT; ++k) {
                u64 d = ffma2(mz2[k], zj, ffma2(my2[k], yj, ffma2(mx2[k], xj, sj)));
                float dl, dh;
                upk2(d, dl, dh);
                cl[k] = fminf(cl[k], dl);
                ch[k] = fminf(ch[k], dh);
            }
        }
    }

    // ---- Phase 2: kNN — 6 smallest within adv (self included; ci-offset dropped) ----
    // Process groups of 2 packed pairs (4 distances): exact sort4 (10 FMNMX),
    // one unconditional insert of the min, nested rare branches for the rest.
    for (int t = 0; t < NTILE; ++t) {
        __syncthreads();
        const float* P = A + (size_t)(t * TILE_J) * 3;
        for (int j = tid; j < TILE_J; j += THREADS) {
            float x = P[3 * j + 0], y = P[3 * j + 1], z = P[3 * j + 2];
            s_x[j] = x; s_y[j] = y; s_z[j] = z;
            s_s[j] = fmaf(x, x, fmaf(y, y, z * z));
        }
        __syncthreads();

        const int pbeg = seg * WPAIRS;
#pragma unroll 2
        for (int p = pbeg; p < pbeg + WPAIRS; p += 2) {
            u64 xj0 = s_x2[p],     yj0 = s_y2[p],     zj0 = s_z2[p],     sj0 = s_s2[p];
            u64 xj1 = s_x2[p + 1], yj1 = s_y2[p + 1], zj1 = s_z2[p + 1], sj1 = s_s2[p + 1];
#pragma unroll
            for (int k = 0; k < IPT; ++k) {
                u64 d0 = ffma2(mz2[k], zj0, ffma2(my2[k], yj0, ffma2(mx2[k], xj0, sj0)));
                u64 d1 = ffma2(mz2[k], zj1, ffma2(my2[k], yj1, ffma2(mx2[k], xj1, sj1)));
                float a, bb, c, d;
                upk2(d0, a, bb);
                upk2(d1, c, d);
                // sort4: s0 <= s1 <= s2 <= s3 (10 FMNMX)
                float t1 = fminf(a, bb), t2 = fmaxf(a, bb);
                float t3 = fminf(c, d),  t4 = fmaxf(c, d);
                float s0 = fminf(t1, t3), m1 = fmaxf(t1, t3);
                float m2 = fminf(t2, t4), s3v = fmaxf(t2, t4);
                float s1v = fminf(m1, m2), s2v = fmaxf(m1, m2);
                // Branchless hot path: group min (no-op if not qualifying)
                insert6(h[k], s0);
                // s1 qualifies ~1.2%/lane (~30%/warp); s2, s3 vanishingly rare.
                // Lanes with !c1 have s2v >= s1v >= h[5], so nested conds stay false.
                bool c1 = s1v < h[k][5];
                if (__any_sync(full, c1)) {
                    if (c1) insert6(h[k], s1v);
                    bool c2 = s2v < h[k][5];
                    if (__any_sync(full, c2)) {
                        if (c2) insert6(h[k], s2v);
                        bool c3 = s3v < h[k][5];
                        if (__any_sync(full, c3)) {
                            if (c3) insert6(h[k], s3v);
                        }
                    }
                }
            }
        }
    }

    // Fold packed chamfer halves
    float cmin[IPT];
#pragma unroll
    for (int k = 0; k < IPT; ++k) cmin[k] = fminf(cl[k], ch[k]);

    // ---- Cross-warp merge (3-round tree), reusing tile smem as buffer ----
    float* buf = sm;

#define MERGE_WRITE(SLOT)                                                   \
    {                                                                       \
        float* w = buf + (((size_t)(SLOT) * 32 + l) * IPT) * 7;             \
        _Pragma("unroll")                                                   \
        for (int k = 0; k < IPT; ++k) {                                     \
            w[k * 7 + 0] = cmin[k];                                         \
            _Pragma("unroll")                                               \
            for (int m = 0; m < 6; ++m) w[k * 7 + 1 + m] = h[k][m];         \
        }                                                                   \
    }
#define MERGE_READ(SLOT)                                                    \
    {                                                                       \
        const float* r = buf + (((size_t)(SLOT) * 32 + l) * IPT) * 7;       \
        _Pragma("unroll")                                                   \
        for (int k = 0; k < IPT; ++k) {                                     \
            cmin[k] = fminf(cmin[k], r[k * 7 + 0]);                         \
            _Pragma("unroll")                                               \
            for (int m = 0; m < 6; ++m) heap_insert(h[k], r[k * 7 + 1 + m]);\
        }                                                                   \
    }

    __syncthreads();
    if (seg >= 4) MERGE_WRITE(seg - 4);
    __syncthreads();
    if (seg < 4) MERGE_READ(seg);
    __syncthreads();
    if (seg == 2 || seg == 3) MERGE_WRITE(seg - 2);
    __syncthreads();
    if (seg < 2) MERGE_READ(seg);
    __syncthreads();
    if (seg == 1) MERGE_WRITE(0);
    __syncthreads();
    if (seg == 0) {
        MERGE_READ(0);
#pragma unroll
        for (int k = 0; k < IPT; ++k) {
            int i = ibase + l + 32 * k;
            g_cham[b * KP + i] = cmin[k] + ci[k];
            // drop h[0] (self), mean of next 5, re-add ci offset
            g_value[b * KP + i] =
                fmaf(0.2f, h[k][1] + h[k][2] + h[k][3] + h[k][4] + h[k][5], ci[k]);
        }
    }
}

// Warp-shuffle block reduction (256 thr): result valid in thread 0.
__device__ __forceinline__ float block_sum(float v, float* red) {
    const unsigned full = 0xffffffffu;
#pragma unroll
    for (int o = 16; o > 0; o >>= 1) v += __shfl_xor_sync(full, v, o);
    const int w = threadIdx.x >> 5;
    if ((threadIdx.x & 31) == 0) red[w] = v;
    __syncthreads();
    float r = 0.0f;
    if (threadIdx.x < 8) r = red[threadIdx.x];
#pragma unroll
    for (int o = 4; o > 0; o >>= 1) r += __shfl_xor_sync(full, r, o);
    __syncthreads();
    return r;   // thread 0 holds the sum
}

__global__ void __launch_bounds__(256)
reduce_kernel() {
    __shared__ float red[8];
    __shared__ float s_bcast[2];
    const int b = blockIdx.x;
    const int tid = threadIdx.x;
    const float* cham = g_cham + b * KP;
    const float* val  = g_value + b * KP;

    float s1 = 0.0f, s2 = 0.0f;
    for (int i = tid; i < KP; i += 256) { s1 += cham[i]; s2 += val[i]; }
    float cham_sum = block_sum(s1, red);
    float val_sum  = block_sum(s2, red);
    if (tid == 0) s_bcast[0] = val_sum * (1.0f / KP);
    __syncthreads();
    float mean = s_bcast[0];

    float s3 = 0.0f;
    for (int i = tid; i < KP; i += 256) {
        float d = val[i] - mean;
        s3 = fmaf(d, d, s3);
    }
    float var_sum = block_sum(s3, red);
    if (tid == 0) {
        float stdv = sqrtf(var_sum * (1.0f / (KP - 1)));   // ddof=1
        s_bcast[1] = fmaf(ALPHA, stdv, mean);
    }
    __syncthreads();
    float thr = s_bcast[1];

    float s4 = 0.0f;
    for (int i = tid; i < KP; i += 256) {
        float v = val[i];
        if (v > thr) s4 += v;
    }
    float msum = block_sum(s4, red);

    if (tid == 0) {
        float cham_mean = cham_sum * (1.0f / KP);
        float knn_mean  = msum * (1.0f / KP);
        g_batch[b] = cham_mean * W_CHAMFER + knn_mean * W_KNN;
    }
}

__global__ void final_kernel(float* __restrict__ out) {
    if (threadIdx.x == 0) {
        float s = 0.0f;
#pragma unroll
        for (int b = 0; b < BP; ++b) s += g_batch[b];
        out[0] = s * (1.0f / BP);
    }
}

extern "C" void kernel_launch(void* const* d_in, const int* in_sizes, int n_in,
                              void* d_out, int out_size) {
    const float* adv = (const float*)d_in[0];
    const float* ori = (const float*)d_in[1];
    float* out = (float*)d_out;

    dist_kernel<<<dim3(KP / TILE_I, BP), THREADS, SMEM_BYTES>>>(adv, ori);
    reduce_kernel<<<BP, 256>>>();
    final_kernel<<<1, 32>>>(out);
}